// round 9
// baseline (speedup 1.0000x reference)
#include <cuda_runtime.h>
#include <cuda_bf16.h>
#include <cstdint>

// Fused gamma-pdf-weighted MSE mean reduction — single kernel, BLOCK-level
// dynamic tile scheduler, 256-bit loads, last-block-done finalize.
//
// mean( 0.5*(output-target)^2 * ef(target) )
// ef(y) = (BETA - c)*(1 - pdf(y)/FX_MAX) + c,  c = 1/(Y_MAX - Y_MIN)
// pdf/FX_MAX < 4e-19 for fp32 uniform targets except exact zeros ->
// log/exp only in a cold branch (y < 1e-6); hot loop has no MUFU.
//
// R9 fix of R8: tile claim is now per-BLOCK (tid0 atomicAdd -> smem
// broadcast, double-barrier to close the read/write race). R8 claimed
// per-thread while indexing per-block -> summed exactly 1/256 of the data.
// Per-thread fp64 accumulation keeps the result independent of the dynamic
// tile->block assignment.

#define NBLK 740                      // 148 SMs * 5
#define NTH  256
#define V8PT 2                        // v8 loads per thread per stream per tile
#define TILE_V8     (NTH * V8PT)      // 512 v8 units
#define TILE_FLOATS (TILE_V8 * 8)     // 4096 floats per stream per tile (16KB)

__device__ double       g_part[NBLK];
__device__ unsigned int g_count;   // completion; self-resets via atomicInc wrap
__device__ unsigned int g_tile;    // work-steal counter; reset by last block

__device__ __forceinline__ float elem_val(float o, float y) {
    const float A1        = -0.9355570857535674f;            // EST_A - 1
    const float NEG_LOC   = 1.1328205299926424e-27f;         // -EST_LOC
    const float INV_SCALE = (float)(1.0 / 1.5376362609160314);
    const float C0        = -58.4492351f;                    // -lgamma(a)-ln(scale)-ln(FX_MAX)
    const float C         = (float)(1.0 / 107.2185);
    const float BC        = 5.0f - (float)(1.0 / 107.2185);

    float r = 0.0f;
    if (y < 1e-6f) {                      // cold path: only (near-)zero targets
        float x  = (y + NEG_LOC) * INV_SCALE;
        float lp = fmaf(A1, __logf(x), C0) - x;
        r = __expf(lp);
    }
    float ef   = fmaf(BC, 1.0f - r, C);
    float diff = o - y;
    return 0.5f * diff * diff * ef;
}

// 256-bit read-only global load (sm_100+): one LDG.E.256 per call.
__device__ __forceinline__ void ldg256(const float* __restrict__ p, float r[8]) {
    asm volatile("ld.global.nc.v8.f32 {%0,%1,%2,%3,%4,%5,%6,%7}, [%8];"
                 : "=f"(r[0]), "=f"(r[1]), "=f"(r[2]), "=f"(r[3]),
                   "=f"(r[4]), "=f"(r[5]), "=f"(r[6]), "=f"(r[7])
                 : "l"(p));
}

__device__ __forceinline__ float oct_val(const float o[8], const float t[8]) {
    float s = 0.0f;
    #pragma unroll
    for (int j = 0; j < 8; ++j) s += elem_val(o[j], t[j]);
    return s;
}

__global__ __launch_bounds__(NTH, 5) void loss_fused_kernel(
    const float* __restrict__ out, const float* __restrict__ tgt,
    float* __restrict__ result, int n)
{
    const int tid  = threadIdx.x;
    const int lane = tid & 31;
    const int warp = tid >> 5;
    const int n8   = n >> 3;
    const unsigned int ntiles = (unsigned int)(n8 / TILE_V8);

    __shared__ unsigned int s_next;
    __shared__ bool         s_last;

    double dsum = 0.0;

    // ---- block-level dynamic tile loop ----
    if (tid == 0) s_next = atomicAdd(&g_tile, 1u);
    __syncthreads();                          // claim visible to all
    unsigned int t = s_next;                  // every thread copies

    while (t < ntiles) {
        __syncthreads();                      // all threads copied s_next -> t
        if (tid == 0) s_next = atomicAdd(&g_tile, 1u);  // prefetch next claim;
                                              // ATOMG latency hides under loads
        const size_t base = (size_t)t * TILE_FLOATS + (size_t)tid * 8;
        float o0[8], t0[8], o1[8], t1[8];
        ldg256(out + base,           o0);
        ldg256(tgt + base,           t0);
        ldg256(out + base + NTH * 8, o1);
        ldg256(tgt + base + NTH * 8, t1);
        float s = oct_val(o0, t0) + oct_val(o1, t1);
        dsum += (double)s;                    // order-insensitive accumulation

        __syncthreads();                      // s_next write visible
        t = s_next;
    }

    // ---- static tail: v8 remainder + scalar remainder ----
    {
        const int idx    = blockIdx.x * NTH + tid;
        const int stride = gridDim.x * NTH;
        float tail = 0.0f;
        for (int i = (int)(ntiles * TILE_V8) + idx; i < n8; i += stride) {
            float o0[8], t0[8];
            ldg256(out + (size_t)i * 8, o0);
            ldg256(tgt + (size_t)i * 8, t0);
            tail += oct_val(o0, t0);
        }
        for (int j = (n8 << 3) + idx; j < n; j += stride)
            tail += elem_val(out[j], tgt[j]);
        dsum += (double)tail;
    }

    // ---- block reduce in fp64 (full-warp shuffles only) ----
    #pragma unroll
    for (int off = 16; off > 0; off >>= 1)
        dsum += __shfl_down_sync(0xFFFFFFFFu, dsum, off);

    __shared__ double s_warp[NTH / 32];
    if (lane == 0) s_warp[warp] = dsum;
    __syncthreads();

    if (warp == 0) {                          // full warp active
        double v = (lane < NTH / 32) ? s_warp[lane] : 0.0;
        #pragma unroll
        for (int off = 16; off > 0; off >>= 1)
            v += __shfl_down_sync(0xFFFFFFFFu, v, off);
        if (lane == 0) {
            g_part[blockIdx.x] = v;
            __threadfence();                                    // release
            unsigned int prev = atomicInc(&g_count, NBLK - 1u); // wraps -> 0
            s_last = (prev == NBLK - 1u);
        }
    }
    __syncthreads();

    if (s_last) {
        __threadfence();                      // acquire before reading g_part
        if (tid == 0)
            atomicExch(&g_tile, 0u);          // reset for graph replay; every
                                              // block's claims happen-before
                                              // its g_count arrival
        double acc = 0.0;                     // fixed-order reduce of partials
        for (int k = tid; k < NBLK; k += NTH)
            acc += g_part[k];

        #pragma unroll
        for (int off = 16; off > 0; off >>= 1)
            acc += __shfl_down_sync(0xFFFFFFFFu, acc, off);

        __shared__ double s_d[NTH / 32];
        if (lane == 0) s_d[warp] = acc;
        __syncthreads();

        if (warp == 0) {                      // full warp active
            double v = (lane < NTH / 32) ? s_d[lane] : 0.0;
            #pragma unroll
            for (int off = 16; off > 0; off >>= 1)
                v += __shfl_down_sync(0xFFFFFFFFu, v, off);
            if (lane == 0)
                result[0] = (float)(v / (double)n);
        }
    }
}

extern "C" void kernel_launch(void* const* d_in, const int* in_sizes, int n_in,
                              void* d_out, int out_size)
{
    const float* output = (const float*)d_in[0];
    const float* target = (const float*)d_in[1];
    const int n = in_sizes[0];

    loss_fused_kernel<<<NBLK, NTH>>>(output, target, (float*)d_out, n);
}

// round 10
// speedup vs baseline: 1.0549x; 1.0549x over previous
#include <cuda_runtime.h>
#include <cuda_bf16.h>
#include <cstdint>

// Fused gamma-pdf-weighted MSE mean reduction — single kernel, last-block-done,
// 256-bit loads, EXACT-BALANCE grid: 1024 blocks x 128 threads = 131072
// threads divides n/8 = 2^21 exactly -> every thread does 16 iterations,
// zero tail, zero balancing synchronization.
//
// mean( 0.5*(output-target)^2 * ef(target) )
// ef(y) = (BETA - c)*(1 - pdf(y)/FX_MAX) + c,  c = 1/(Y_MAX - Y_MIN)
// pdf/FX_MAX < 4e-19 for fp32 uniform targets except exact zeros ->
// log/exp only in a cold branch (y < 1e-6); hot loop has no MUFU.
//
// R10 rationale: R9's dynamic scheduler regressed (per-tile barriers killed
// cross-iteration MLP). The imbalance fix must be free: choose a power-of-2
// thread count dividing the workload. Generic remainder loops retained for
// other n (empty for this shape).

#define NBLK 1024
#define NTH  128

__device__ float        g_part[NBLK];
__device__ unsigned int g_count;   // zero-init; self-resetting via atomicInc wrap

__device__ __forceinline__ float elem_val(float o, float y) {
    const float A1        = -0.9355570857535674f;            // EST_A - 1
    const float NEG_LOC   = 1.1328205299926424e-27f;         // -EST_LOC
    const float INV_SCALE = (float)(1.0 / 1.5376362609160314);
    const float C0        = -58.4492351f;                    // -lgamma(a)-ln(scale)-ln(FX_MAX)
    const float C         = (float)(1.0 / 107.2185);
    const float BC        = 5.0f - (float)(1.0 / 107.2185);

    float r = 0.0f;
    if (y < 1e-6f) {                      // cold path: only (near-)zero targets
        float x  = (y + NEG_LOC) * INV_SCALE;
        float lp = fmaf(A1, __logf(x), C0) - x;
        r = __expf(lp);
    }
    float ef   = fmaf(BC, 1.0f - r, C);
    float diff = o - y;
    return 0.5f * diff * diff * ef;
}

// 256-bit read-only global load (sm_100+): one LDG.E.256 per call.
__device__ __forceinline__ void ldg256(const float* __restrict__ p, float r[8]) {
    asm volatile("ld.global.nc.v8.f32 {%0,%1,%2,%3,%4,%5,%6,%7}, [%8];"
                 : "=f"(r[0]), "=f"(r[1]), "=f"(r[2]), "=f"(r[3]),
                   "=f"(r[4]), "=f"(r[5]), "=f"(r[6]), "=f"(r[7])
                 : "l"(p));
}

__device__ __forceinline__ float oct_val(const float o[8], const float t[8]) {
    float s = 0.0f;
    #pragma unroll
    for (int j = 0; j < 8; ++j) s += elem_val(o[j], t[j]);
    return s;
}

__global__ __launch_bounds__(NTH) void loss_fused_kernel(
    const float* __restrict__ out, const float* __restrict__ tgt,
    float* __restrict__ result, int n)
{
    const int tid    = threadIdx.x;
    const int lane   = tid & 31;
    const int warp   = tid >> 5;
    const int idx    = blockIdx.x * NTH + tid;
    const int stride = gridDim.x * NTH;      // 131072, divides n/8 for n=2^24
    const int n8     = n >> 3;               // v8 chunks

    float sum = 0.0f;
    int i = idx;

    // Unroll-by-2: 4 x LDG.E.256 issued before compute (128B in flight/thread).
    for (; i + stride < n8; i += 2 * stride) {
        float o0[8], t0[8], o1[8], t1[8];
        ldg256(out + (size_t)i * 8,            o0);
        ldg256(tgt + (size_t)i * 8,            t0);
        ldg256(out + (size_t)(i + stride) * 8, o1);
        ldg256(tgt + (size_t)(i + stride) * 8, t1);
        sum += oct_val(o0, t0);
        sum += oct_val(o1, t1);
    }
    for (; i < n8; i += stride) {          // v8 remainder
        float o0[8], t0[8];
        ldg256(out + (size_t)i * 8, o0);
        ldg256(tgt + (size_t)i * 8, t0);
        sum += oct_val(o0, t0);
    }
    for (int j = (n8 << 3) + idx; j < n; j += stride)   // scalar tail (empty here)
        sum += elem_val(out[j], tgt[j]);

    // ---- block reduce (full-warp shuffles only) ----
    #pragma unroll
    for (int off = 16; off > 0; off >>= 1)
        sum += __shfl_down_sync(0xFFFFFFFFu, sum, off);

    __shared__ float s_warp[NTH / 32];
    __shared__ bool  s_last;
    if (lane == 0) s_warp[warp] = sum;
    __syncthreads();

    if (warp == 0) {                      // full warp active
        float v = (lane < NTH / 32) ? s_warp[lane] : 0.0f;
        #pragma unroll
        for (int off = 16; off > 0; off >>= 1)
            v += __shfl_down_sync(0xFFFFFFFFu, v, off);
        if (lane == 0) {
            g_part[blockIdx.x] = v;
            __threadfence();                                   // release
            unsigned int prev = atomicInc(&g_count, NBLK - 1u); // wraps -> 0
            s_last = (prev == NBLK - 1u);
        }
    }
    __syncthreads();

    if (s_last) {
        __threadfence();                  // acquire before reading g_part
        double acc = 0.0;                 // fixed-order deterministic reduce
        for (int k = tid; k < NBLK; k += NTH)
            acc += (double)g_part[k];

        #pragma unroll
        for (int off = 16; off > 0; off >>= 1)
            acc += __shfl_down_sync(0xFFFFFFFFu, acc, off);

        __shared__ double s_d[NTH / 32];
        if (lane == 0) s_d[warp] = acc;
        __syncthreads();

        if (warp == 0) {                  // full warp active
            double v = (lane < NTH / 32) ? s_d[lane] : 0.0;
            #pragma unroll
            for (int off = 16; off > 0; off >>= 1)
                v += __shfl_down_sync(0xFFFFFFFFu, v, off);
            if (lane == 0)
                result[0] = (float)(v / (double)n);
        }
    }
}

extern "C" void kernel_launch(void* const* d_in, const int* in_sizes, int n_in,
                              void* d_out, int out_size)
{
    const float* output = (const float*)d_in[0];
    const float* target = (const float*)d_in[1];
    const int n = in_sizes[0];

    loss_fused_kernel<<<NBLK, NTH>>>(output, target, (float*)d_out, n);
}

// round 11
// speedup vs baseline: 1.0757x; 1.0197x over previous
#include <cuda_runtime.h>
#include <cuda_bf16.h>
#include <cstdint>

// Fused gamma-pdf-weighted MSE mean reduction — single kernel, last-block-done,
// 256-bit loads + L2 software prefetch (decouple DRAM fill from L1 tracking).
//
// mean( 0.5*(output-target)^2 * ef(target) )
// ef(y) = (BETA - c)*(1 - pdf(y)/FX_MAX) + c,  c = 1/(Y_MAX - Y_MIN)
// pdf/FX_MAX < 4e-19 for fp32 uniform targets except exact zeros ->
// log/exp only in a cold branch (y < 1e-6); hot loop has no MUFU.
//
// R11 rationale: all load paths plateau at ~5.06 TB/s independent of MLP and
// occupancy -> SM-side outstanding-request tracking is occupancy-time
// limited (rate = entries / latency). prefetch.global.L2 is fire-and-forget
// (no L1 tracking entry); issued one pair-iteration (~5us, 24MB) ahead it
// converts demand-load latency from DRAM (~600-1000cyc) to L2-hit (~240cyc),
// turning each tracking entry over ~3x faster.

#define NBLK 740    // 148 SMs * 5
#define NTH  256

__device__ float        g_part[NBLK];
__device__ unsigned int g_count;   // zero-init; self-resetting via atomicInc wrap

__device__ __forceinline__ float elem_val(float o, float y) {
    const float A1        = -0.9355570857535674f;            // EST_A - 1
    const float NEG_LOC   = 1.1328205299926424e-27f;         // -EST_LOC
    const float INV_SCALE = (float)(1.0 / 1.5376362609160314);
    const float C0        = -58.4492351f;                    // -lgamma(a)-ln(scale)-ln(FX_MAX)
    const float C         = (float)(1.0 / 107.2185);
    const float BC        = 5.0f - (float)(1.0 / 107.2185);

    float r = 0.0f;
    if (y < 1e-6f) {                      // cold path: only (near-)zero targets
        float x  = (y + NEG_LOC) * INV_SCALE;
        float lp = fmaf(A1, __logf(x), C0) - x;
        r = __expf(lp);
    }
    float ef   = fmaf(BC, 1.0f - r, C);
    float diff = o - y;
    return 0.5f * diff * diff * ef;
}

// 256-bit read-only global load (sm_100+): one LDG.E.256 per call.
__device__ __forceinline__ void ldg256(const float* __restrict__ p, float r[8]) {
    asm volatile("ld.global.nc.v8.f32 {%0,%1,%2,%3,%4,%5,%6,%7}, [%8];"
                 : "=f"(r[0]), "=f"(r[1]), "=f"(r[2]), "=f"(r[3]),
                   "=f"(r[4]), "=f"(r[5]), "=f"(r[6]), "=f"(r[7])
                 : "l"(p));
}

// Fire-and-forget DRAM->L2 prefetch; no L1 tracking entry, no writeback.
__device__ __forceinline__ void prefetch_l2(const float* p) {
    asm volatile("prefetch.global.L2 [%0];" :: "l"(p));
}

__device__ __forceinline__ float oct_val(const float o[8], const float t[8]) {
    float s = 0.0f;
    #pragma unroll
    for (int j = 0; j < 8; ++j) s += elem_val(o[j], t[j]);
    return s;
}

__global__ __launch_bounds__(NTH, 5) void loss_fused_kernel(
    const float* __restrict__ out, const float* __restrict__ tgt,
    float* __restrict__ result, int n)
{
    const int tid    = threadIdx.x;
    const int lane   = tid & 31;
    const int warp   = tid >> 5;
    const int idx    = blockIdx.x * NTH + tid;
    const int stride = gridDim.x * NTH;
    const int n8     = n >> 3;            // v8 chunks
    const int PFD    = 2 * stride;        // one unrolled pair-iteration ahead

    float sum = 0.0f;
    int i = idx;

    // Unroll-by-2: 4 x LDG.E.256 issued before compute; prefetch next pair.
    for (; i + stride < n8; i += 2 * stride) {
        // L2 prefetch one pair-iteration ahead (one lane per 128B line).
        if ((lane & 3) == 0 && i + PFD + stride < n8) {
            prefetch_l2(out + (size_t)(i + PFD) * 8);
            prefetch_l2(tgt + (size_t)(i + PFD) * 8);
            prefetch_l2(out + (size_t)(i + PFD + stride) * 8);
            prefetch_l2(tgt + (size_t)(i + PFD + stride) * 8);
        }
        float o0[8], t0[8], o1[8], t1[8];
        ldg256(out + (size_t)i * 8,            o0);
        ldg256(tgt + (size_t)i * 8,            t0);
        ldg256(out + (size_t)(i + stride) * 8, o1);
        ldg256(tgt + (size_t)(i + stride) * 8, t1);
        sum += oct_val(o0, t0);
        sum += oct_val(o1, t1);
    }
    for (; i < n8; i += stride) {          // v8 remainder
        float o0[8], t0[8];
        ldg256(out + (size_t)i * 8, o0);
        ldg256(tgt + (size_t)i * 8, t0);
        sum += oct_val(o0, t0);
    }
    for (int j = (n8 << 3) + idx; j < n; j += stride)   // scalar tail
        sum += elem_val(out[j], tgt[j]);

    // ---- block reduce (full-warp shuffles only) ----
    #pragma unroll
    for (int off = 16; off > 0; off >>= 1)
        sum += __shfl_down_sync(0xFFFFFFFFu, sum, off);

    __shared__ float s_warp[NTH / 32];
    __shared__ bool  s_last;
    if (lane == 0) s_warp[warp] = sum;
    __syncthreads();

    if (warp == 0) {                      // full warp active
        float v = (lane < NTH / 32) ? s_warp[lane] : 0.0f;
        #pragma unroll
        for (int off = 16; off > 0; off >>= 1)
            v += __shfl_down_sync(0xFFFFFFFFu, v, off);
        if (lane == 0) {
            g_part[blockIdx.x] = v;
            __threadfence();                                   // release
            unsigned int prev = atomicInc(&g_count, NBLK - 1u); // wraps -> 0
            s_last = (prev == NBLK - 1u);
        }
    }
    __syncthreads();

    if (s_last) {
        __threadfence();                  // acquire before reading g_part
        double acc = 0.0;                 // fixed-order deterministic reduce
        for (int k = tid; k < NBLK; k += NTH)
            acc += (double)g_part[k];

        #pragma unroll
        for (int off = 16; off > 0; off >>= 1)
            acc += __shfl_down_sync(0xFFFFFFFFu, acc, off);

        __shared__ double s_d[NTH / 32];
        if (lane == 0) s_d[warp] = acc;
        __syncthreads();

        if (warp == 0) {                  // full warp active
            double v = (lane < NTH / 32) ? s_d[lane] : 0.0;
            #pragma unroll
            for (int off = 16; off > 0; off >>= 1)
                v += __shfl_down_sync(0xFFFFFFFFu, v, off);
            if (lane == 0)
                result[0] = (float)(v / (double)n);
        }
    }
}

extern "C" void kernel_launch(void* const* d_in, const int* in_sizes, int n_in,
                              void* d_out, int out_size)
{
    const float* output = (const float*)d_in[0];
    const float* target = (const float*)d_in[1];
    const int n = in_sizes[0];

    loss_fused_kernel<<<NBLK, NTH>>>(output, target, (float*)d_out, n);
}